// round 14
// baseline (speedup 1.0000x reference)
#include <cuda_runtime.h>
#include <cuda_bf16.h>
#include <math.h>
#include <stdint.h>

// ---------------------------------------------------------------------------
// unit_gcn: stage-1 HMMA (mma.sync m16n8k16 bf16, 3-term split via K-concat,
// two A halves, cp.async fills), stage-2 scalar f32x2 on ALL 256 threads
// (thread = (o, t-half, w-half), uniform control flow), smem-staged coalesced
// epilogue.  4 frames/block, 256 threads, 2 CTAs/SM.  (base: R13 = 723us)
// ---------------------------------------------------------------------------

typedef unsigned long long ull;

__device__ __forceinline__ ull pk2(float lo, float hi) {
    ull r; asm("mov.b64 %0, {%1, %2};" : "=l"(r) : "f"(lo), "f"(hi)); return r;
}
__device__ __forceinline__ void fma2(ull &d, ull a, ull b) {
    asm("fma.rn.f32x2 %0, %1, %2, %0;" : "+l"(d) : "l"(a), "l"(b));
}
__device__ __forceinline__ float2 up2(ull v) {
    float2 r; asm("mov.b64 {%0, %1}, %2;" : "=f"(r.x), "=f"(r.y) : "l"(v)); return r;
}
__device__ __forceinline__ uint32_t smem_u32(const void* p) {
    uint32_t a;
    asm("{ .reg .u64 t; cvta.to.shared.u64 t, %1; cvt.u32.u64 %0, t; }"
        : "=r"(a) : "l"(p));
    return a;
}
__device__ __forceinline__ void cp16(uint32_t dst, const void* src) {
    asm volatile("cp.async.cg.shared.global [%0], [%1], 16;"
                 :: "r"(dst), "l"(src) : "memory");
}
__device__ __forceinline__ void cp_commit_wait() {
    asm volatile("cp.async.commit_group;" ::: "memory");
    asm volatile("cp.async.wait_group 0;" ::: "memory");
}
__device__ __forceinline__ void ldsm_x4(uint32_t &r0, uint32_t &r1,
                                        uint32_t &r2, uint32_t &r3, uint32_t a) {
    asm volatile("ldmatrix.sync.aligned.m8n8.x4.shared.b16 {%0,%1,%2,%3}, [%4];"
                 : "=r"(r0), "=r"(r1), "=r"(r2), "=r"(r3) : "r"(a));
}
__device__ __forceinline__ void ldsm_x2(uint32_t &r0, uint32_t &r1, uint32_t a) {
    asm volatile("ldmatrix.sync.aligned.m8n8.x2.shared.b16 {%0,%1}, [%2];"
                 : "=r"(r0), "=r"(r1) : "r"(a));
}
__device__ __forceinline__ void mma_bf16(float* d, const uint32_t* a,
                                         uint32_t b0, uint32_t b1) {
    asm volatile(
        "mma.sync.aligned.m16n8k16.row.col.f32.bf16.bf16.f32 "
        "{%0,%1,%2,%3}, {%4,%5,%6,%7}, {%8,%9}, {%0,%1,%2,%3};"
        : "+f"(d[0]), "+f"(d[1]), "+f"(d[2]), "+f"(d[3])
        : "r"(a[0]), "r"(a[1]), "r"(a[2]), "r"(a[3]), "r"(b0), "r"(b1));
}

// ------------------------- smem layout (bytes) ------------------------------
#define AH_OFF     0
#define AH_BYTES   39936
#define B_OFF      39936
#define AFS_OFF    89088
#define KC_OFF     97488
#define SMEM_BYTES 97792
#define P_OFF      0
#define P_STRIDE   116
#define YS_OFF     0               /* ys[64][100] f32, overlays P after stage2 */

// ------------------------- device scratch (no allocs) ----------------------
__device__ __nv_bfloat16 d_Aimg2[2 * 192 * 104]; // A' per k-half, row pitch 104
__device__ float d_Afp[75 * 28];                 // Af padded stride 28
__device__ float d_Kc[64];
__device__ float d_pp[64 * 128 * 1600];          // per-(ttile,n) partial sums
__device__ float d_g[128 * 64 * 25];

// ------------------------------- prep --------------------------------------
__global__ void prep_kernel(const float* __restrict__ A, const float* __restrict__ PA,
                            const float* __restrict__ wd, const float* __restrict__ bd,
                            const float* __restrict__ gamma, const float* __restrict__ beta,
                            const float* __restrict__ mean, const float* __restrict__ var)
{
    int tid = threadIdx.x;
    __shared__ float ssc[64];
    if (tid < 64) {
        float sc = gamma[tid] * rsqrtf(var[tid] + 1e-5f);
        ssc[tid] = sc;
        d_Kc[tid] = (bd[tid] + bd[64 + tid] + bd[128 + tid]) * sc
                    + beta[tid] - mean[tid] * sc;
    }
    __syncthreads();
    for (int idx = tid; idx < 75; idx += blockDim.x) {
        int s = idx / 25, w = idx % 25;
        float nrm = 0.f;
        for (int v = 0; v < 25; v++) {
            float pv = PA[(s * 25 + v) * 25 + w];
            nrm += pv * pv;
        }
        nrm = sqrtf(nrm) + 1e-4f;
        for (int v = 0; v < 25; v++)
            d_Afp[(s * 25 + v) * 28 + w] =
                A[(s * 25 + v) * 25 + w] + PA[(s * 25 + v) * 25 + w] / nrm;
        d_Afp[idx * 28 + 25] = 0.f;
        d_Afp[idx * 28 + 26] = 0.f;
        d_Afp[idx * 28 + 27] = 0.f;
    }
    // A' image: half h, row (s,o), local kc<96 -> global k = h*96+kc,
    // K segs over c: [Whi | Whi | Wlo]
    for (int e = tid; e < 2 * 192 * 104; e += blockDim.x) {
        int h   = e / (192 * 104);
        int rem = e - h * 192 * 104;
        int row = rem / 104, kc = rem - row * 104;
        float val = 0.f;
        if (kc < 96) {
            int k = h * 96 + kc;
            int s = row >> 6, o = row & 63;
            int seg = k >> 6, c = k & 63;
            float w = wd[(s * 64 + o) * 64 + c] * ssc[o];
            float hi = __bfloat162float(__float2bfloat16(w));
            val = (seg < 2) ? hi : (w - hi);
        }
        d_Aimg2[e] = __float2bfloat16(val);
    }
}

// ------------------------------- main ---------------------------------------
__global__ void __launch_bounds__(256, 2)
main_kernel(const float* __restrict__ x, float* __restrict__ out)
{
    extern __shared__ char smc[];
    const uint32_t smb = smem_u32(smc);
    const int tid  = threadIdx.x;
    const int wrp  = tid >> 5;
    const int lane = tid & 31;
    const int n    = blockIdx.y;
    const int t0   = blockIdx.x * 4;

    // ---- fill: A half0 via cp.async (overlaps B' conversion), B', Af, Kc ----
    {
        const char* srcA = (const char*)d_Aimg2;
        #pragma unroll
        for (int i = 0; i < 10; i++) {
            int e = (tid + i * 256) * 16;
            if (e < AH_BYTES) cp16(smb + AH_OFF + e, srcA + e);
        }
        asm volatile("cp.async.commit_group;" ::: "memory");

        const float* xb = x + (size_t)n * 409600 + t0 * 25;
        __nv_bfloat16* smB = (__nv_bfloat16*)(smc + B_OFF);
        for (int e = tid; e < 6400; e += 256) {
            int c = e / 100, r = e - c * 100;
            float xv = xb[c * 6400 + r];
            __nv_bfloat16 h = __float2bfloat16(xv);
            __nv_bfloat16 l = __float2bfloat16(xv - __bfloat162float(h));
            __nv_bfloat16* br = smB + r * 200;
            br[c]       = h;
            br[64 + c]  = l;
            br[128 + c] = h;
        }
        float* Afs = (float*)(smc + AFS_OFF);
        for (int i = tid; i < 75 * 28; i += 256) Afs[i] = d_Afp[i];
        float* Kcs = (float*)(smc + KC_OFF);
        if (tid < 64) Kcs[tid] = d_Kc[tid];
        asm volatile("cp.async.wait_group 0;" ::: "memory");
    }
    __syncthreads();

    // ---- stage 1: HMMA, warp (mw,nw) owns 48 x 56 of P[192][112] ----
    const int mw = wrp >> 1;
    const int nw = wrp & 1;

    float acc[3][7][4];
    #pragma unroll
    for (int i = 0; i < 3; i++)
        #pragma unroll
        for (int j = 0; j < 7; j++)
            #pragma unroll
            for (int q = 0; q < 4; q++) acc[i][j][q] = 0.f;

    const uint32_t aLane = (((lane & 7) + ((lane >> 3) & 1) * 8) * 208
                            + ((lane >> 4) & 1) * 16);
    const uint32_t aBase = smb + AH_OFF + (uint32_t)(mw * 48) * 208u + aLane;
    const uint32_t bLane4 = ((lane & 7) * 400 + ((lane >> 3) & 1) * 16
                             + ((lane >> 4) & 1) * 3200);
    const uint32_t bBase4 = smb + B_OFF + (uint32_t)(nw * 56) * 400u + bLane4;
    const uint32_t bBase2 = smb + B_OFF + (uint32_t)(nw * 56 + 48) * 400u
                            + (lane & 7) * 400 + ((lane >> 3) & 1) * 16;

    #pragma unroll
    for (int h = 0; h < 2; h++) {
        if (h == 1) {
            __syncthreads();       // half-0 ldsm reads done
            const char* srcA = (const char*)d_Aimg2 + AH_BYTES;
            #pragma unroll
            for (int i = 0; i < 10; i++) {
                int e = (tid + i * 256) * 16;
                if (e < AH_BYTES) cp16(smb + AH_OFF + e, srcA + e);
            }
            cp_commit_wait();
            __syncthreads();
        }
        #pragma unroll 2
        for (int ksl = 0; ksl < 6; ksl++) {
            const uint32_t ko = (uint32_t)ksl * 32u;
            const uint32_t kb = (uint32_t)(h * 6 + ksl) * 32u;
            uint32_t af[3][4];
            #pragma unroll
            for (int i = 0; i < 3; i++)
                ldsm_x4(af[i][0], af[i][1], af[i][2], af[i][3],
                        aBase + (uint32_t)i * 3328u + ko);
            #pragma unroll
            for (int jj = 0; jj < 3; jj++) {
                uint32_t q0, q1, q2, q3;
                ldsm_x4(q0, q1, q2, q3, bBase4 + (uint32_t)jj * 6400u + kb);
                #pragma unroll
                for (int i = 0; i < 3; i++) {
                    mma_bf16(acc[i][2 * jj],     af[i], q0, q1);
                    mma_bf16(acc[i][2 * jj + 1], af[i], q2, q3);
                }
            }
            {
                uint32_t b0, b1;
                ldsm_x2(b0, b1, bBase2 + kb);
                #pragma unroll
                for (int i = 0; i < 3; i++)
                    mma_bf16(acc[i][6], af[i], b0, b1);
            }
        }
    }
    __syncthreads();   // all ldsm reads done; A/B region dead

    // ---- write P[192][116] f32 ----
    float* Psf = (float*)(smc + P_OFF);
    {
        const int rl = lane >> 2;
        const int cl = (lane & 3) * 2;
        #pragma unroll
        for (int i = 0; i < 3; i++) {
            int r0 = mw * 48 + i * 16 + rl;
            #pragma unroll
            for (int j = 0; j < 7; j++) {
                int c = nw * 56 + j * 8 + cl;
                *(float2*)&Psf[r0 * P_STRIDE + c] =
                    make_float2(acc[i][j][0], acc[i][j][1]);
                *(float2*)&Psf[(r0 + 8) * P_STRIDE + c] =
                    make_float2(acc[i][j][2], acc[i][j][3]);
            }
        }
    }
    __syncthreads();

    // ---- stage 2 (256 threads): thread = (o, t-half, w-half) ----
    // wh=0 computes w-pairs 0..6, wh=1 computes w-pairs 6..12 (uniform code,
    // pair 6 redundantly computed by both halves).
    const int o  = tid >> 2;
    const int th = (tid >> 1) & 1;
    const int wh = tid & 1;

    ull yacc[2][7];
    #pragma unroll
    for (int u = 0; u < 2; u++)
        #pragma unroll
        for (int p = 0; p < 7; p++) yacc[u][p] = 0ull;

    {
        const float* Afs = (const float*)(smc + AFS_OFF);
        #pragma unroll
        for (int s = 0; s < 3; s++) {
            const float* pb = Psf + (s * 64 + o) * P_STRIDE + (2 * th) * 25;
            const char* afb = (const char*)(Afs + s * 25 * 28) + wh * 48;
            #pragma unroll 5
            for (int v = 0; v < 25; v++) {
                const char* ar = afb + v * 112;
                ulonglong2 q0 = *(const ulonglong2*)(ar);
                ulonglong2 q1 = *(const ulonglong2*)(ar + 16);
                ulonglong2 q2 = *(const ulonglong2*)(ar + 32);
                ull q3 = *(const ull*)(ar + 48);
                float pf0 = pb[v];
                float pf1 = pb[25 + v];
                ull pv0 = pk2(pf0, pf0);
                ull pv1 = pk2(pf1, pf1);
                fma2(yacc[0][0], pv0, q0.x);  fma2(yacc[0][1], pv0, q0.y);
                fma2(yacc[0][2], pv0, q1.x);  fma2(yacc[0][3], pv0, q1.y);
                fma2(yacc[0][4], pv0, q2.x);  fma2(yacc[0][5], pv0, q2.y);
                fma2(yacc[0][6], pv0, q3);
                fma2(yacc[1][0], pv1, q0.x);  fma2(yacc[1][1], pv1, q0.y);
                fma2(yacc[1][2], pv1, q1.x);  fma2(yacc[1][3], pv1, q1.y);
                fma2(yacc[1][4], pv1, q2.x);  fma2(yacc[1][5], pv1, q2.y);
                fma2(yacc[1][6], pv1, q3);
            }
        }
    }
    __syncthreads();          // all P reads done; overlay ys on P region

    // ---- stage 2b: dump raw y to ys[64][100] ----
    float* ys = (float*)(smc + YS_OFF);
    {
        #pragma unroll
        for (int u = 0; u < 2; u++) {
            float* yr = ys + o * 100 + (2 * th + u) * 25;
            if (wh == 0) {
                #pragma unroll
                for (int p = 0; p < 7; p++) {
                    float2 t2 = up2(yacc[u][p]);
                    yr[2 * p]     = t2.x;
                    yr[2 * p + 1] = t2.y;
                }
            } else {
                #pragma unroll
                for (int p = 1; p < 6; p++) {
                    float2 t2 = up2(yacc[u][p]);
                    yr[12 + 2 * p] = t2.x;
                    yr[13 + 2 * p] = t2.y;
                }
                yr[24] = up2(yacc[u][6]).x;
            }
        }
    }
    __syncthreads();

    // ---- epilogue pass (coalesced): yfinal = relu(y + kc + x); store out ----
    {
        const float* Kcs = (const float*)(smc + KC_OFF);
        const float* xb = x + (size_t)n * 409600 + t0 * 25;
        float* ob = out + (size_t)n * 409600 + t0 * 25;
        #pragma unroll
        for (int e = tid; e < 6400; e += 256) {
            int oo = e / 100, r = e - oo * 100;
            float yf = fmaxf(ys[e] + Kcs[oo] + xb[oo * 6400 + r], 0.f);
            ob[oo * 6400 + r] = yf;
            ys[e] = yf;
        }
    }
    __syncthreads();

    // ---- T-sum pass: d_pp[(blk,n)][o*25+w] = sum_t ys[o][t*25+w] ----
    {
        float* pout = d_pp + ((size_t)blockIdx.x * 128 + n) * 1600;
        for (int idx = tid; idx < 1600; idx += 256) {
            int oo = idx / 25, w = idx - oo * 25;
            const float* yr = ys + oo * 100 + w;
            pout[idx] = (yr[0] + yr[25]) + (yr[50] + yr[75]);
        }
    }
}

// ------------------------------- gate ---------------------------------------
__global__ void gate_kernel(const float* __restrict__ ws, const float* __restrict__ bs,
                            const float* __restrict__ we, const float* __restrict__ be)
{
    __shared__ float p[1600];
    __shared__ float sbuf[100];
    const int n = blockIdx.x, tid = threadIdx.x;   // 256 threads
    for (int idx = tid; idx < 1600; idx += 256) {
        float a0 = 0.f, a1 = 0.f, a2 = 0.f, a3 = 0.f;
        for (int tile = 0; tile < 64; tile += 4) {
            a0 += d_pp[((size_t)(tile + 0) * 128 + n) * 1600 + idx];
            a1 += d_pp[((size_t)(tile + 1) * 128 + n) * 1600 + idx];
            a2 += d_pp[((size_t)(tile + 2) * 128 + n) * 1600 + idx];
            a3 += d_pp[((size_t)(tile + 3) * 128 + n) * 1600 + idx];
        }
        p[idx] = ((a0 + a1) + (a2 + a3)) * (1.0f / 256.0f);
    }
    __syncthreads();
    if (tid < 100) {
        int r = tid / 25, v = tid % 25;
        float acc = bs[r];
        int k0 = 12 - v; if (k0 < 0) k0 = 0;
        int k1 = 36 - v; if (k1 > 24) k1 = 24;
        for (int c = 0; c < 64; c++) {
            const float* wr = &ws[(r * 64 + c) * 25];
            const float* pc = &p[c * 25 + v - 12];
            for (int k = k0; k <= k1; k++)
                acc = fmaf(pc[k], wr[k], acc);
        }
        sbuf[tid] = fmaxf(acc, 0.f);
    }
    __syncthreads();
    for (int idx = tid; idx < 1600; idx += 256) {
        int o = idx / 25, v = idx % 25;
        float z = be[o];
        #pragma unroll
        for (int r = 0; r < 4; r++)
            z = fmaf(sbuf[r * 25 + v], we[o * 4 + r], z);
        d_g[n * 1600 + idx] = 1.f + 1.f / (1.f + expf(-z));
    }
}

// ------------------------------- final --------------------------------------
__global__ void final_kernel(float* __restrict__ out)
{
    unsigned i = blockIdx.x * blockDim.x + threadIdx.x;
    float4 v = reinterpret_cast<float4*>(out)[i];
    unsigned flat = i * 4u;
    unsigned q  = flat / 25u;
    unsigned v0 = flat - q * 25u;
    unsigned co = q / 256u;
    const float* gr = d_g + (size_t)co * 25u;
    unsigned v1 = v0 + 1u; if (v1 >= 25u) v1 -= 25u;
    unsigned v2 = v0 + 2u; if (v2 >= 25u) v2 -= 25u;
    unsigned v3 = v0 + 3u; if (v3 >= 25u) v3 -= 25u;
    v.x *= gr[v0]; v.y *= gr[v1]; v.z *= gr[v2]; v.w *= gr[v3];
    reinterpret_cast<float4*>(out)[i] = v;
}

// ------------------------------ launcher -------------------------------------
extern "C" void kernel_launch(void* const* d_in, const int* in_sizes, int n_in,
                              void* d_out, int out_size)
{
    const float* x     = (const float*)d_in[0];
    const float* A     = (const float*)d_in[1];
    const float* PA    = (const float*)d_in[2];
    const float* wd    = (const float*)d_in[3];
    const float* bd    = (const float*)d_in[4];
    const float* gamma = (const float*)d_in[5];
    const float* beta  = (const float*)d_in[6];
    const float* mean  = (const float*)d_in[7];
    const float* var   = (const float*)d_in[8];
    const float* sws   = (const float*)d_in[9];
    const float* sbs   = (const float*)d_in[10];
    const float* swe   = (const float*)d_in[11];
    const float* sbe   = (const float*)d_in[12];
    float* out = (float*)d_out;

    cudaFuncSetAttribute(main_kernel, cudaFuncAttributeMaxDynamicSharedMemorySize,
                         SMEM_BYTES);

    prep_kernel<<<1, 256>>>(A, PA, wd, bd, gamma, beta, mean, var);
    dim3 grid(64, 128);
    main_kernel<<<grid, 256, SMEM_BYTES>>>(x, out);
    gate_kernel<<<128, 256>>>(sws, sbs, swe, sbe);
    final_kernel<<<51200, 256>>>(out);
}

// round 15
// speedup vs baseline: 1.0290x; 1.0290x over previous
#include <cuda_runtime.h>
#include <cuda_bf16.h>
#include <math.h>
#include <stdint.h>

// ---------------------------------------------------------------------------
// unit_gcn: stage-1 HMMA (mma.sync m16n8k16 bf16, 3-term split via K-concat,
// two A halves, cp.async fills, B' seg-dedup [Xhi|Xlo]), stage-2 scalar f32x2
// with t-pairing (128 threads x 2 frames, Af warp-broadcast), smem-staged
// coalesced epilogue.  4 frames/block, 256 threads, 2 CTAs/SM.
// (base: R13 = 723us; change: B' dedup, k-steps 8-11 remap to seg 0)
// ---------------------------------------------------------------------------

typedef unsigned long long ull;

__device__ __forceinline__ ull pk2(float lo, float hi) {
    ull r; asm("mov.b64 %0, {%1, %2};" : "=l"(r) : "f"(lo), "f"(hi)); return r;
}
__device__ __forceinline__ void fma2(ull &d, ull a, ull b) {
    asm("fma.rn.f32x2 %0, %1, %2, %0;" : "+l"(d) : "l"(a), "l"(b));
}
__device__ __forceinline__ float2 up2(ull v) {
    float2 r; asm("mov.b64 {%0, %1}, %2;" : "=f"(r.x), "=f"(r.y) : "l"(v)); return r;
}
__device__ __forceinline__ uint32_t smem_u32(const void* p) {
    uint32_t a;
    asm("{ .reg .u64 t; cvta.to.shared.u64 t, %1; cvt.u32.u64 %0, t; }"
        : "=r"(a) : "l"(p));
    return a;
}
__device__ __forceinline__ void cp16(uint32_t dst, const void* src) {
    asm volatile("cp.async.cg.shared.global [%0], [%1], 16;"
                 :: "r"(dst), "l"(src) : "memory");
}
__device__ __forceinline__ void cp_commit_wait() {
    asm volatile("cp.async.commit_group;" ::: "memory");
    asm volatile("cp.async.wait_group 0;" ::: "memory");
}
__device__ __forceinline__ void ldsm_x4(uint32_t &r0, uint32_t &r1,
                                        uint32_t &r2, uint32_t &r3, uint32_t a) {
    asm volatile("ldmatrix.sync.aligned.m8n8.x4.shared.b16 {%0,%1,%2,%3}, [%4];"
                 : "=r"(r0), "=r"(r1), "=r"(r2), "=r"(r3) : "r"(a));
}
__device__ __forceinline__ void ldsm_x2(uint32_t &r0, uint32_t &r1, uint32_t a) {
    asm volatile("ldmatrix.sync.aligned.m8n8.x2.shared.b16 {%0,%1}, [%2];"
                 : "=r"(r0), "=r"(r1) : "r"(a));
}
__device__ __forceinline__ void mma_bf16(float* d, const uint32_t* a,
                                         uint32_t b0, uint32_t b1) {
    asm volatile(
        "mma.sync.aligned.m16n8k16.row.col.f32.bf16.bf16.f32 "
        "{%0,%1,%2,%3}, {%4,%5,%6,%7}, {%8,%9}, {%0,%1,%2,%3};"
        : "+f"(d[0]), "+f"(d[1]), "+f"(d[2]), "+f"(d[3])
        : "r"(a[0]), "r"(a[1]), "r"(a[2]), "r"(a[3]), "r"(b0), "r"(b1));
}

// ------------------------- smem layout (bytes) ------------------------------
// A-half buf: 192 rows x 208B (k-half = 96 bf16)          [0, 39936)
// B':         112 rows x 272B ([Xhi|Xlo], 128 bf16 cols)  [39936, 70400)
// P (overlay after MMA): 192 x 116 f32                    [0, 89088)
// Af: 75 x 28 f32                                         [89088, 97488)
// Kc: 64 f32                                              [97488, 97744)
#define AH_OFF     0
#define AH_BYTES   39936
#define B_OFF      39936
#define B_PITCH    272
#define AFS_OFF    89088
#define KC_OFF     97488
#define SMEM_BYTES 97792
#define P_OFF      0
#define P_STRIDE   116
#define YS_OFF     0               /* ys[64][100] f32, overlays P after stage2 */

// ------------------------- device scratch (no allocs) ----------------------
__device__ __nv_bfloat16 d_Aimg2[2 * 192 * 104]; // A' per k-half, row pitch 104
__device__ float d_Afp[75 * 28];                 // Af padded stride 28
__device__ float d_Kc[64];
__device__ float d_pp[64 * 128 * 1600];          // per-(ttile,n) partial sums
__device__ float d_g[128 * 64 * 25];

// ------------------------------- prep --------------------------------------
__global__ void prep_kernel(const float* __restrict__ A, const float* __restrict__ PA,
                            const float* __restrict__ wd, const float* __restrict__ bd,
                            const float* __restrict__ gamma, const float* __restrict__ beta,
                            const float* __restrict__ mean, const float* __restrict__ var)
{
    int tid = threadIdx.x;
    __shared__ float ssc[64];
    if (tid < 64) {
        float sc = gamma[tid] * rsqrtf(var[tid] + 1e-5f);
        ssc[tid] = sc;
        d_Kc[tid] = (bd[tid] + bd[64 + tid] + bd[128 + tid]) * sc
                    + beta[tid] - mean[tid] * sc;
    }
    __syncthreads();
    for (int idx = tid; idx < 75; idx += blockDim.x) {
        int s = idx / 25, w = idx % 25;
        float nrm = 0.f;
        for (int v = 0; v < 25; v++) {
            float pv = PA[(s * 25 + v) * 25 + w];
            nrm += pv * pv;
        }
        nrm = sqrtf(nrm) + 1e-4f;
        for (int v = 0; v < 25; v++)
            d_Afp[(s * 25 + v) * 28 + w] =
                A[(s * 25 + v) * 25 + w] + PA[(s * 25 + v) * 25 + w] / nrm;
        d_Afp[idx * 28 + 25] = 0.f;
        d_Afp[idx * 28 + 26] = 0.f;
        d_Afp[idx * 28 + 27] = 0.f;
    }
    // A' image: half h, row (s,o), local kc<96 -> global k = h*96+kc,
    // K segs over c: [Whi | Whi | Wlo]
    for (int e = tid; e < 2 * 192 * 104; e += blockDim.x) {
        int h   = e / (192 * 104);
        int rem = e - h * 192 * 104;
        int row = rem / 104, kc = rem - row * 104;
        float val = 0.f;
        if (kc < 96) {
            int k = h * 96 + kc;
            int s = row >> 6, o = row & 63;
            int seg = k >> 6, c = k & 63;
            float w = wd[(s * 64 + o) * 64 + c] * ssc[o];
            float hi = __bfloat162float(__float2bfloat16(w));
            val = (seg < 2) ? hi : (w - hi);
        }
        d_Aimg2[e] = __float2bfloat16(val);
    }
}

// ------------------------------- main ---------------------------------------
__global__ void __launch_bounds__(256, 2)
main_kernel(const float* __restrict__ x, float* __restrict__ out)
{
    extern __shared__ char smc[];
    const uint32_t smb = smem_u32(smc);
    const int tid  = threadIdx.x;
    const int wrp  = tid >> 5;
    const int lane = tid & 31;
    const int n    = blockIdx.y;
    const int t0   = blockIdx.x * 4;

    // ---- fill: A half0 via cp.async (overlaps B' conversion), B', Af, Kc ----
    {
        const char* srcA = (const char*)d_Aimg2;
        #pragma unroll
        for (int i = 0; i < 10; i++) {
            int e = (tid + i * 256) * 16;
            if (e < AH_BYTES) cp16(smb + AH_OFF + e, srcA + e);
        }
        asm volatile("cp.async.commit_group;" ::: "memory");

        const float* xb = x + (size_t)n * 409600 + t0 * 25;
        __nv_bfloat16* smB = (__nv_bfloat16*)(smc + B_OFF);
        for (int e = tid; e < 6400; e += 256) {
            int c = e / 100, r = e - c * 100;
            float xv = xb[c * 6400 + r];
            __nv_bfloat16 h = __float2bfloat16(xv);
            __nv_bfloat16 l = __float2bfloat16(xv - __bfloat162float(h));
            __nv_bfloat16* br = smB + r * 136;   // 272B pitch
            br[c]      = h;
            br[64 + c] = l;
        }
        float* Afs = (float*)(smc + AFS_OFF);
        for (int i = tid; i < 75 * 28; i += 256) Afs[i] = d_Afp[i];
        float* Kcs = (float*)(smc + KC_OFF);
        if (tid < 64) Kcs[tid] = d_Kc[tid];
        asm volatile("cp.async.wait_group 0;" ::: "memory");
    }
    __syncthreads();

    // ---- stage 1: HMMA, warp (mw,nw) owns 48 x 56 of P[192][112] ----
    const int mw = wrp >> 1;
    const int nw = wrp & 1;

    float acc[3][7][4];
    #pragma unroll
    for (int i = 0; i < 3; i++)
        #pragma unroll
        for (int j = 0; j < 7; j++)
            #pragma unroll
            for (int q = 0; q < 4; q++) acc[i][j][q] = 0.f;

    const uint32_t aLane = (((lane & 7) + ((lane >> 3) & 1) * 8) * 208
                            + ((lane >> 4) & 1) * 16);
    const uint32_t aBase = smb + AH_OFF + (uint32_t)(mw * 48) * 208u + aLane;
    const uint32_t bLane4 = ((lane & 7) * B_PITCH + ((lane >> 3) & 1) * 16
                             + ((lane >> 4) & 1) * (8 * B_PITCH));
    const uint32_t bBase4 = smb + B_OFF + (uint32_t)(nw * 56) * B_PITCH + bLane4;
    const uint32_t bBase2 = smb + B_OFF + (uint32_t)(nw * 56 + 48) * B_PITCH
                            + (lane & 7) * B_PITCH + ((lane >> 3) & 1) * 16;

    #pragma unroll
    for (int h = 0; h < 2; h++) {
        if (h == 1) {
            __syncthreads();       // half-0 ldsm reads done
            const char* srcA = (const char*)d_Aimg2 + AH_BYTES;
            #pragma unroll
            for (int i = 0; i < 10; i++) {
                int e = (tid + i * 256) * 16;
                if (e < AH_BYTES) cp16(smb + AH_OFF + e, srcA + e);
            }
            cp_commit_wait();
            __syncthreads();
        }
        #pragma unroll 2
        for (int ksl = 0; ksl < 6; ksl++) {
            const int step = h * 6 + ksl;
            const uint32_t ko = (uint32_t)ksl * 32u;
            // seg-dedup: steps 8..11 read the same Xhi as steps 0..3
            const uint32_t kb = (uint32_t)((step < 8 ? step : step - 8) * 32);
            uint32_t af[3][4];
            #pragma unroll
            for (int i = 0; i < 3; i++)
                ldsm_x4(af[i][0], af[i][1], af[i][2], af[i][3],
                        aBase + (uint32_t)i * 3328u + ko);
            #pragma unroll
            for (int jj = 0; jj < 3; jj++) {
                uint32_t q0, q1, q2, q3;
                ldsm_x4(q0, q1, q2, q3,
                        bBase4 + (uint32_t)jj * (16 * B_PITCH) + kb);
                #pragma unroll
                for (int i = 0; i < 3; i++) {
                    mma_bf16(acc[i][2 * jj],     af[i], q0, q1);
                    mma_bf16(acc[i][2 * jj + 1], af[i], q2, q3);
                }
            }
            {
                uint32_t b0, b1;
                ldsm_x2(b0, b1, bBase2 + kb);
                #pragma unroll
                for (int i = 0; i < 3; i++)
                    mma_bf16(acc[i][6], af[i], b0, b1);
            }
        }
    }
    __syncthreads();   // all ldsm reads done; A/B region dead

    // ---- write P[192][116] f32 ----
    float* Psf = (float*)(smc + P_OFF);
    {
        const int rl = lane >> 2;
        const int cl = (lane & 3) * 2;
        #pragma unroll
        for (int i = 0; i < 3; i++) {
            int r0 = mw * 48 + i * 16 + rl;
            #pragma unroll
            for (int j = 0; j < 7; j++) {
                int c = nw * 56 + j * 8 + cl;
                *(float2*)&Psf[r0 * P_STRIDE + c] =
                    make_float2(acc[i][j][0], acc[i][j][1]);
                *(float2*)&Psf[(r0 + 8) * P_STRIDE + c] =
                    make_float2(acc[i][j][2], acc[i][j][3]);
            }
        }
    }
    __syncthreads();

    // ---- stage 2 (t-paired): thread = (o, t-half); 128 active threads ----
    const int o  = (tid >> 1) & 63;
    const int th = tid & 1;              // frames 2*th, 2*th+1

    ull yacc[2][13];
    if (tid < 128) {
        #pragma unroll
        for (int u = 0; u < 2; u++)
            #pragma unroll
            for (int wp = 0; wp < 13; wp++) yacc[u][wp] = 0ull;

        const float* Afs = (const float*)(smc + AFS_OFF);
        #pragma unroll
        for (int s = 0; s < 3; s++) {
            const float* pb = Psf + (s * 64 + o) * P_STRIDE + (2 * th) * 25;
            const char* afb = (const char*)(Afs + s * 25 * 28);
            #pragma unroll 5
            for (int v = 0; v < 25; v++) {
                const char* ar = afb + v * 112;
                ulonglong2 q0 = *(const ulonglong2*)(ar);
                ulonglong2 q1 = *(const ulonglong2*)(ar + 16);
                ulonglong2 q2 = *(const ulonglong2*)(ar + 32);
                ulonglong2 q3 = *(const ulonglong2*)(ar + 48);
                ulonglong2 q4 = *(const ulonglong2*)(ar + 64);
                ulonglong2 q5 = *(const ulonglong2*)(ar + 80);
                ull q6 = *(const ull*)(ar + 96);
                float pf0 = pb[v];
                float pf1 = pb[25 + v];
                ull pv0 = pk2(pf0, pf0);
                ull pv1 = pk2(pf1, pf1);
                fma2(yacc[0][0],  pv0, q0.x);  fma2(yacc[0][1],  pv0, q0.y);
                fma2(yacc[0][2],  pv0, q1.x);  fma2(yacc[0][3],  pv0, q1.y);
                fma2(yacc[0][4],  pv0, q2.x);  fma2(yacc[0][5],  pv0, q2.y);
                fma2(yacc[0][6],  pv0, q3.x);  fma2(yacc[0][7],  pv0, q3.y);
                fma2(yacc[0][8],  pv0, q4.x);  fma2(yacc[0][9],  pv0, q4.y);
                fma2(yacc[0][10], pv0, q5.x);  fma2(yacc[0][11], pv0, q5.y);
                fma2(yacc[0][12], pv0, q6);
                fma2(yacc[1][0],  pv1, q0.x);  fma2(yacc[1][1],  pv1, q0.y);
                fma2(yacc[1][2],  pv1, q1.x);  fma2(yacc[1][3],  pv1, q1.y);
                fma2(yacc[1][4],  pv1, q2.x);  fma2(yacc[1][5],  pv1, q2.y);
                fma2(yacc[1][6],  pv1, q3.x);  fma2(yacc[1][7],  pv1, q3.y);
                fma2(yacc[1][8],  pv1, q4.x);  fma2(yacc[1][9],  pv1, q4.y);
                fma2(yacc[1][10], pv1, q5.x);  fma2(yacc[1][11], pv1, q5.y);
                fma2(yacc[1][12], pv1, q6);
            }
        }
    }
    __syncthreads();          // all P reads done; overlay ys on P region

    // ---- stage 2b: dump raw y to ys[64][100] ----
    float* ys = (float*)(smc + YS_OFF);
    if (tid < 128) {
        #pragma unroll
        for (int u = 0; u < 2; u++) {
            float* yr = ys + o * 100 + (2 * th + u) * 25;
            #pragma unroll
            for (int wp = 0; wp < 12; wp++) {
                float2 t2 = up2(yacc[u][wp]);
                yr[2 * wp]     = t2.x;
                yr[2 * wp + 1] = t2.y;
            }
            yr[24] = up2(yacc[u][12]).x;
        }
    }
    __syncthreads();

    // ---- epilogue pass (coalesced): yfinal = relu(y + kc + x); store out ----
    {
        const float* Kcs = (const float*)(smc + KC_OFF);
        const float* xb = x + (size_t)n * 409600 + t0 * 25;
        float* ob = out + (size_t)n * 409600 + t0 * 25;
        #pragma unroll
        for (int e = tid; e < 6400; e += 256) {
            int oo = e / 100, r = e - oo * 100;
            float yf = fmaxf(ys[e] + Kcs[oo] + xb[oo * 6400 + r], 0.f);
            ob[oo * 6400 + r] = yf;
            ys[e] = yf;
        }
    }
    __syncthreads();

    // ---- T-sum pass: d_pp[(blk,n)][o*25+w] = sum_t ys[o][t*25+w] ----
    {
        float* pout = d_pp + ((size_t)blockIdx.x * 128 + n) * 1600;
        for (int idx = tid; idx < 1600; idx += 256) {
            int oo = idx / 25, w = idx - oo * 25;
            const float* yr = ys + oo * 100 + w;
            pout[idx] = (yr[0] + yr[25]) + (yr[50] + yr[75]);
        }
    }
}

// ------------------------------- gate ---------------------------------------
__global__ void gate_kernel(const float* __restrict__ ws, const float* __restrict__ bs,
                            const float* __restrict__ we, const float* __restrict__ be)
{
    __shared__ float p[1600];
    __shared__ float sbuf[100];
    const int n = blockIdx.x, tid = threadIdx.x;   // 256 threads
    for (int idx = tid; idx < 1600; idx += 256) {
        float a0 = 0.f, a1 = 0.f, a2 = 0.f, a3 = 0.f;
        for (int tile = 0; tile < 64; tile += 4) {
            a0 += d_pp[((size_t)(tile + 0) * 128 + n) * 1600 + idx];
            a1 += d_pp[((size_t)(tile + 1) * 128 + n) * 1600 + idx];
            a2 += d_pp[((size_t)(tile + 2) * 128 + n) * 1600 + idx];
            a3 += d_pp[((size_t)(tile + 3) * 128 + n) * 1600 + idx];
        }
        p[idx] = ((a0 + a1) + (a2 + a3)) * (1.0f / 256.0f);
    }
    __syncthreads();
    if (tid < 100) {
        int r = tid / 25, v = tid % 25;
        float acc = bs[r];
        int k0 = 12 - v; if (k0 < 0) k0 = 0;
        int k1 = 36 - v; if (k1 > 24) k1 = 24;
        for (int c = 0; c < 64; c++) {
            const float* wr = &ws[(r * 64 + c) * 25];
            const float* pc = &p[c * 25 + v - 12];
            for (int k = k0; k <= k1; k++)
                acc = fmaf(pc[k], wr[k], acc);
        }
        sbuf[tid] = fmaxf(acc, 0.f);
    }
    __syncthreads();
    for (int idx = tid; idx < 1600; idx += 256) {
        int o = idx / 25, v = idx % 25;
        float z = be[o];
        #pragma unroll
        for (int r = 0; r < 4; r++)
            z = fmaf(sbuf[r * 25 + v], we[o * 4 + r], z);
        d_g[n * 1600 + idx] = 1.f + 1.f / (1.f + expf(-z));
    }
}

// ------------------------------- final --------------------------------------
__global__ void final_kernel(float* __restrict__ out)
{
    unsigned i = blockIdx.x * blockDim.x + threadIdx.x;
    float4 v = reinterpret_cast<float4*>(out)[i];
    unsigned flat = i * 4u;
    unsigned q  = flat / 25u;
    unsigned v0 = flat - q * 25u;
    unsigned co = q / 256u;
    const float* gr = d_g + (size_t)co * 25u;
    unsigned v1 = v0 + 1u; if (v1 >= 25u) v1 -= 25u;
    unsigned v2 = v0 + 2u; if (v2 >= 25u) v2 -= 25u;
    unsigned v3 = v0 + 3u; if (v3 >= 25u) v3 -= 25u;
    v.x *= gr[v0]; v.y *= gr[v1]; v.z *= gr[v2]; v.w *= gr[v3];
    reinterpret_cast<float4*>(out)[i] = v;
}

// ------------------------------ launcher -------------------------------------
extern "C" void kernel_launch(void* const* d_in, const int* in_sizes, int n_in,
                              void* d_out, int out_size)
{
    const float* x     = (const float*)d_in[0];
    const float* A     = (const float*)d_in[1];
    const float* PA    = (const float*)d_in[2];
    const float* wd    = (const float*)d_in[3];
    const float* bd    = (const float*)d_in[4];
    const float* gamma = (const float*)d_in[5];
    const float* beta  = (const float*)d_in[6];
    const float* mean  = (const float*)d_in[7];
    const float* var   = (const float*)d_in[8];
    const float* sws   = (const float*)d_in[9];
    const float* sbs   = (const float*)d_in[10];
    const float* swe   = (const float*)d_in[11];
    const float* sbe   = (const float*)d_in[12];
    float* out = (float*)d_out;

    cudaFuncSetAttribute(main_kernel, cudaFuncAttributeMaxDynamicSharedMemorySize,
                         SMEM_BYTES);

    prep_kernel<<<1, 256>>>(A, PA, wd, bd, gamma, beta, mean, var);
    dim3 grid(64, 128);
    main_kernel<<<grid, 256, SMEM_BYTES>>>(x, out);
    gate_kernel<<<128, 256>>>(sws, sbs, swe, sbe);
    final_kernel<<<51200, 256>>>(out);
}

// round 16
// speedup vs baseline: 1.1259x; 1.0942x over previous
#include <cuda_runtime.h>
#include <cuda_bf16.h>
#include <math.h>
#include <stdint.h>

// ---------------------------------------------------------------------------
// unit_gcn: stage-1 HMMA (mma.sync m16n8k16 bf16, 3-term split via K-concat,
// two A halves, cp.async fills, B' seg-dedup [Xhi|Xlo]), stage-2 scalar f32x2
// with t-pairing, smem-staged coalesced epilogue.  4 frames/block, 256 thr,
// 2 CTAs/SM.  R16: prep split (parallel A' image build), gate conv spread.
// ---------------------------------------------------------------------------

typedef unsigned long long ull;

__device__ __forceinline__ ull pk2(float lo, float hi) {
    ull r; asm("mov.b64 %0, {%1, %2};" : "=l"(r) : "f"(lo), "f"(hi)); return r;
}
__device__ __forceinline__ void fma2(ull &d, ull a, ull b) {
    asm("fma.rn.f32x2 %0, %1, %2, %0;" : "+l"(d) : "l"(a), "l"(b));
}
__device__ __forceinline__ float2 up2(ull v) {
    float2 r; asm("mov.b64 {%0, %1}, %2;" : "=f"(r.x), "=f"(r.y) : "l"(v)); return r;
}
__device__ __forceinline__ uint32_t smem_u32(const void* p) {
    uint32_t a;
    asm("{ .reg .u64 t; cvta.to.shared.u64 t, %1; cvt.u32.u64 %0, t; }"
        : "=r"(a) : "l"(p));
    return a;
}
__device__ __forceinline__ void cp16(uint32_t dst, const void* src) {
    asm volatile("cp.async.cg.shared.global [%0], [%1], 16;"
                 :: "r"(dst), "l"(src) : "memory");
}
__device__ __forceinline__ void cp_commit_wait() {
    asm volatile("cp.async.commit_group;" ::: "memory");
    asm volatile("cp.async.wait_group 0;" ::: "memory");
}
__device__ __forceinline__ void ldsm_x4(uint32_t &r0, uint32_t &r1,
                                        uint32_t &r2, uint32_t &r3, uint32_t a) {
    asm volatile("ldmatrix.sync.aligned.m8n8.x4.shared.b16 {%0,%1,%2,%3}, [%4];"
                 : "=r"(r0), "=r"(r1), "=r"(r2), "=r"(r3) : "r"(a));
}
__device__ __forceinline__ void ldsm_x2(uint32_t &r0, uint32_t &r1, uint32_t a) {
    asm volatile("ldmatrix.sync.aligned.m8n8.x2.shared.b16 {%0,%1}, [%2];"
                 : "=r"(r0), "=r"(r1) : "r"(a));
}
__device__ __forceinline__ void mma_bf16(float* d, const uint32_t* a,
                                         uint32_t b0, uint32_t b1) {
    asm volatile(
        "mma.sync.aligned.m16n8k16.row.col.f32.bf16.bf16.f32 "
        "{%0,%1,%2,%3}, {%4,%5,%6,%7}, {%8,%9}, {%0,%1,%2,%3};"
        : "+f"(d[0]), "+f"(d[1]), "+f"(d[2]), "+f"(d[3])
        : "r"(a[0]), "r"(a[1]), "r"(a[2]), "r"(a[3]), "r"(b0), "r"(b1));
}

// ------------------------- smem layout (bytes) ------------------------------
#define AH_OFF     0
#define AH_BYTES   39936
#define B_OFF      39936
#define B_PITCH    272
#define AFS_OFF    89088
#define KC_OFF     97488
#define SMEM_BYTES 97792
#define P_OFF      0
#define P_STRIDE   116
#define YS_OFF     0               /* ys[64][100] f32, overlays P after stage2 */

// ------------------------- device scratch (no allocs) ----------------------
__device__ __nv_bfloat16 d_Aimg2[2 * 192 * 104]; // A' per k-half, row pitch 104
__device__ float d_Afp[75 * 28];                 // Af padded stride 28
__device__ float d_Kc[64];
__device__ float d_pp[64 * 128 * 1600];          // per-(ttile,n) partial sums
__device__ float d_g[128 * 64 * 25];

// ------------------------------- prep1 (serial small parts) ----------------
__global__ void prep1_kernel(const float* __restrict__ A, const float* __restrict__ PA,
                             const float* __restrict__ bd,
                             const float* __restrict__ gamma, const float* __restrict__ beta,
                             const float* __restrict__ mean, const float* __restrict__ var)
{
    int tid = threadIdx.x;
    if (tid < 64) {
        float sc = gamma[tid] * rsqrtf(var[tid] + 1e-5f);
        d_Kc[tid] = (bd[tid] + bd[64 + tid] + bd[128 + tid]) * sc
                    + beta[tid] - mean[tid] * sc;
    }
    for (int idx = tid; idx < 75; idx += blockDim.x) {
        int s = idx / 25, w = idx % 25;
        float nrm = 0.f;
        for (int v = 0; v < 25; v++) {
            float pv = PA[(s * 25 + v) * 25 + w];
            nrm += pv * pv;
        }
        nrm = sqrtf(nrm) + 1e-4f;
        for (int v = 0; v < 25; v++)
            d_Afp[(s * 25 + v) * 28 + w] =
                A[(s * 25 + v) * 25 + w] + PA[(s * 25 + v) * 25 + w] / nrm;
        d_Afp[idx * 28 + 25] = 0.f;
        d_Afp[idx * 28 + 26] = 0.f;
        d_Afp[idx * 28 + 27] = 0.f;
    }
}

// ------------------------------- prep2 (parallel A' image) -----------------
// 64 blocks x 256 threads, grid-stride over 2*192*104 elements.
__global__ void prep2_kernel(const float* __restrict__ wd,
                             const float* __restrict__ gamma,
                             const float* __restrict__ var)
{
    const int stride = gridDim.x * blockDim.x;
    for (int e = blockIdx.x * blockDim.x + threadIdx.x; e < 2 * 192 * 104;
         e += stride) {
        int h   = e / (192 * 104);
        int rem = e - h * 192 * 104;
        int row = rem / 104, kc = rem - row * 104;
        float val = 0.f;
        if (kc < 96) {
            int k = h * 96 + kc;
            int s = row >> 6, o = row & 63;
            int seg = k >> 6, c = k & 63;
            float sc = gamma[o] * rsqrtf(var[o] + 1e-5f);
            float w = wd[(s * 64 + o) * 64 + c] * sc;
            float hi = __bfloat162float(__float2bfloat16(w));
            val = (seg < 2) ? hi : (w - hi);
        }
        d_Aimg2[e] = __float2bfloat16(val);
    }
}

// ------------------------------- main ---------------------------------------
__global__ void __launch_bounds__(256, 2)
main_kernel(const float* __restrict__ x, float* __restrict__ out)
{
    extern __shared__ char smc[];
    const uint32_t smb = smem_u32(smc);
    const int tid  = threadIdx.x;
    const int wrp  = tid >> 5;
    const int lane = tid & 31;
    const int n    = blockIdx.y;
    const int t0   = blockIdx.x * 4;

    // ---- fill: A half0 via cp.async (overlaps B' conversion), B', Af, Kc ----
    {
        const char* srcA = (const char*)d_Aimg2;
        #pragma unroll
        for (int i = 0; i < 10; i++) {
            int e = (tid + i * 256) * 16;
            if (e < AH_BYTES) cp16(smb + AH_OFF + e, srcA + e);
        }
        asm volatile("cp.async.commit_group;" ::: "memory");

        const float* xb = x + (size_t)n * 409600 + t0 * 25;
        __nv_bfloat16* smB = (__nv_bfloat16*)(smc + B_OFF);
        for (int e = tid; e < 6400; e += 256) {
            int c = e / 100, r = e - c * 100;
            float xv = xb[c * 6400 + r];
            __nv_bfloat16 h = __float2bfloat16(xv);
            __nv_bfloat16 l = __float2bfloat16(xv - __bfloat162float(h));
            __nv_bfloat16* br = smB + r * 136;   // 272B pitch
            br[c]      = h;
            br[64 + c] = l;
        }
        float* Afs = (float*)(smc + AFS_OFF);
        for (int i = tid; i < 75 * 28; i += 256) Afs[i] = d_Afp[i];
        float* Kcs = (float*)(smc + KC_OFF);
        if (tid < 64) Kcs[tid] = d_Kc[tid];
        asm volatile("cp.async.wait_group 0;" ::: "memory");
    }
    __syncthreads();

    // ---- stage 1: HMMA, warp (mw,nw) owns 48 x 56 of P[192][112] ----
    const int mw = wrp >> 1;
    const int nw = wrp & 1;

    float acc[3][7][4];
    #pragma unroll
    for (int i = 0; i < 3; i++)
        #pragma unroll
        for (int j = 0; j < 7; j++)
            #pragma unroll
            for (int q = 0; q < 4; q++) acc[i][j][q] = 0.f;

    const uint32_t aLane = (((lane & 7) + ((lane >> 3) & 1) * 8) * 208
                            + ((lane >> 4) & 1) * 16);
    const uint32_t aBase = smb + AH_OFF + (uint32_t)(mw * 48) * 208u + aLane;
    const uint32_t bLane4 = ((lane & 7) * B_PITCH + ((lane >> 3) & 1) * 16
                             + ((lane >> 4) & 1) * (8 * B_PITCH));
    const uint32_t bBase4 = smb + B_OFF + (uint32_t)(nw * 56) * B_PITCH + bLane4;
    const uint32_t bBase2 = smb + B_OFF + (uint32_t)(nw * 56 + 48) * B_PITCH
                            + (lane & 7) * B_PITCH + ((lane >> 3) & 1) * 16;

    #pragma unroll
    for (int h = 0; h < 2; h++) {
        if (h == 1) {
            __syncthreads();       // half-0 ldsm reads done
            const char* srcA = (const char*)d_Aimg2 + AH_BYTES;
            #pragma unroll
            for (int i = 0; i < 10; i++) {
                int e = (tid + i * 256) * 16;
                if (e < AH_BYTES) cp16(smb + AH_OFF + e, srcA + e);
            }
            cp_commit_wait();
            __syncthreads();
        }
        #pragma unroll 2
        for (int ksl = 0; ksl < 6; ksl++) {
            const int step = h * 6 + ksl;
            const uint32_t ko = (uint32_t)ksl * 32u;
            // seg-dedup: steps 8..11 read the same Xhi as steps 0..3
            const uint32_t kb = (uint32_t)((step < 8 ? step : step - 8) * 32);
            uint32_t af[3][4];
            #pragma unroll
            for (int i = 0; i < 3; i++)
                ldsm_x4(af[i][0], af[i][1], af[i][2], af[i][3],
                        aBase + (uint32_t)i * 3328u + ko);
            #pragma unroll
            for (int jj = 0; jj < 3; jj++) {
                uint32_t q0, q1, q2, q3;
                ldsm_x4(q0, q1, q2, q3,
                        bBase4 + (uint32_t)jj * (16 * B_PITCH) + kb);
                #pragma unroll
                for (int i = 0; i < 3; i++) {
                    mma_bf16(acc[i][2 * jj],     af[i], q0, q1);
                    mma_bf16(acc[i][2 * jj + 1], af[i], q2, q3);
                }
            }
            {
                uint32_t b0, b1;
                ldsm_x2(b0, b1, bBase2 + kb);
                #pragma unroll
                for (int i = 0; i < 3; i++)
                    mma_bf16(acc[i][6], af[i], b0, b1);
            }
        }
    }
    __syncthreads();   // all ldsm reads done; A/B region dead

    // ---- write P[192][116] f32 ----
    float* Psf = (float*)(smc + P_OFF);
    {
        const int rl = lane >> 2;
        const int cl = (lane & 3) * 2;
        #pragma unroll
        for (int i = 0; i < 3; i++) {
            int r0 = mw * 48 + i * 16 + rl;
            #pragma unroll
            for (int j = 0; j < 7; j++) {
                int c = nw * 56 + j * 8 + cl;
                *(float2*)&Psf[r0 * P_STRIDE + c] =
                    make_float2(acc[i][j][0], acc[i][j][1]);
                *(float2*)&Psf[(r0 + 8) * P_STRIDE + c] =
                    make_float2(acc[i][j][2], acc[i][j][3]);
            }
        }
    }
    __syncthreads();

    // ---- stage 2 (t-paired): thread = (o, t-half); 128 active threads ----
    const int o  = (tid >> 1) & 63;
    const int th = tid & 1;              // frames 2*th, 2*th+1

    ull yacc[2][13];
    if (tid < 128) {
        #pragma unroll
        for (int u = 0; u < 2; u++)
            #pragma unroll
            for (int wp = 0; wp < 13; wp++) yacc[u][wp] = 0ull;

        const float* Afs = (const float*)(smc + AFS_OFF);
        #pragma unroll
        for (int s = 0; s < 3; s++) {
            const float* pb = Psf + (s * 64 + o) * P_STRIDE + (2 * th) * 25;
            const char* afb = (const char*)(Afs + s * 25 * 28);
            #pragma unroll 5
            for (int v = 0; v < 25; v++) {
                const char* ar = afb + v * 112;
                ulonglong2 q0 = *(const ulonglong2*)(ar);
                ulonglong2 q1 = *(const ulonglong2*)(ar + 16);
                ulonglong2 q2 = *(const ulonglong2*)(ar + 32);
                ulonglong2 q3 = *(const ulonglong2*)(ar + 48);
                ulonglong2 q4 = *(const ulonglong2*)(ar + 64);
                ulonglong2 q5 = *(const ulonglong2*)(ar + 80);
                ull q6 = *(const ull*)(ar + 96);
                float pf0 = pb[v];
                float pf1 = pb[25 + v];
                ull pv0 = pk2(pf0, pf0);
                ull pv1 = pk2(pf1, pf1);
                fma2(yacc[0][0],  pv0, q0.x);  fma2(yacc[0][1],  pv0, q0.y);
                fma2(yacc[0][2],  pv0, q1.x);  fma2(yacc[0][3],  pv0, q1.y);
                fma2(yacc[0][4],  pv0, q2.x);  fma2(yacc[0][5],  pv0, q2.y);
                fma2(yacc[0][6],  pv0, q3.x);  fma2(yacc[0][7],  pv0, q3.y);
                fma2(yacc[0][8],  pv0, q4.x);  fma2(yacc[0][9],  pv0, q4.y);
                fma2(yacc[0][10], pv0, q5.x);  fma2(yacc[0][11], pv0, q5.y);
                fma2(yacc[0][12], pv0, q6);
                fma2(yacc[1][0],  pv1, q0.x);  fma2(yacc[1][1],  pv1, q0.y);
                fma2(yacc[1][2],  pv1, q1.x);  fma2(yacc[1][3],  pv1, q1.y);
                fma2(yacc[1][4],  pv1, q2.x);  fma2(yacc[1][5],  pv1, q2.y);
                fma2(yacc[1][6],  pv1, q3.x);  fma2(yacc[1][7],  pv1, q3.y);
                fma2(yacc[1][8],  pv1, q4.x);  fma2(yacc[1][9],  pv1, q4.y);
                fma2(yacc[1][10], pv1, q5.x);  fma2(yacc[1][11], pv1, q5.y);
                fma2(yacc[1][12], pv1, q6);
            }
        }
    }
    __syncthreads();          // all P reads done; overlay ys on P region

    // ---- stage 2b: dump raw y to ys[64][100] ----
    float* ys = (float*)(smc + YS_OFF);
    if (tid < 128) {
        #pragma unroll
        for (int u = 0; u < 2; u++) {
            float* yr = ys + o * 100 + (2 * th + u) * 25;
            #pragma unroll
            for (int wp = 0; wp < 12; wp++) {
                float2 t2 = up2(yacc[u][wp]);
                yr[2 * wp]     = t2.x;
                yr[2 * wp + 1] = t2.y;
            }
            yr[24] = up2(yacc[u][12]).x;
        }
    }
    __syncthreads();

    // ---- epilogue pass (coalesced): yfinal = relu(y + kc + x); store out ----
    {
        const float* Kcs = (const float*)(smc + KC_OFF);
        const float* xb = x + (size_t)n * 409600 + t0 * 25;
        float* ob = out + (size_t)n * 409600 + t0 * 25;
        #pragma unroll
        for (int e = tid; e < 6400; e += 256) {
            int oo = e / 100, r = e - oo * 100;
            float yf = fmaxf(ys[e] + Kcs[oo] + xb[oo * 6400 + r], 0.f);
            ob[oo * 6400 + r] = yf;
            ys[e] = yf;
        }
    }
    __syncthreads();

    // ---- T-sum pass: d_pp[(blk,n)][o*25+w] = sum_t ys[o][t*25+w] ----
    {
        float* pout = d_pp + ((size_t)blockIdx.x * 128 + n) * 1600;
        for (int idx = tid; idx < 1600; idx += 256) {
            int oo = idx / 25, w = idx - oo * 25;
            const float* yr = ys + oo * 100 + w;
            pout[idx] = (yr[0] + yr[25]) + (yr[50] + yr[75]);
        }
    }
}

// ------------------------------- gate ---------------------------------------
__global__ void gate_kernel(const float* __restrict__ ws, const float* __restrict__ bs,
                            const float* __restrict__ we, const float* __restrict__ be)
{
    __shared__ float p[1600];
    __shared__ float part[200];
    __shared__ float sbuf[100];
    const int n = blockIdx.x, tid = threadIdx.x;   // 256 threads
    for (int idx = tid; idx < 1600; idx += 256) {
        float a0 = 0.f, a1 = 0.f, a2 = 0.f, a3 = 0.f;
        for (int tile = 0; tile < 64; tile += 4) {
            a0 += d_pp[((size_t)(tile + 0) * 128 + n) * 1600 + idx];
            a1 += d_pp[((size_t)(tile + 1) * 128 + n) * 1600 + idx];
            a2 += d_pp[((size_t)(tile + 2) * 128 + n) * 1600 + idx];
            a3 += d_pp[((size_t)(tile + 3) * 128 + n) * 1600 + idx];
        }
        p[idx] = ((a0 + a1) + (a2 + a3)) * (1.0f / 256.0f);
    }
    __syncthreads();
    // conv spread over 200 threads: worker = (rv, c-half of 32)
    if (tid < 200) {
        int half = tid / 100;
        int rv = tid - half * 100;
        int r = rv / 25, v = rv % 25;
        float acc = (half == 0) ? bs[r] : 0.f;
        int k0 = 12 - v; if (k0 < 0) k0 = 0;
        int k1 = 36 - v; if (k1 > 24) k1 = 24;
        int c0 = half * 32;
        for (int c = c0; c < c0 + 32; c++) {
            const float* wr = &ws[(r * 64 + c) * 25];
            const float* pc = &p[c * 25 + v - 12];
            for (int k = k0; k <= k1; k++)
                acc = fmaf(pc[k], wr[k], acc);
        }
        part[tid] = acc;
    }
    __syncthreads();
    if (tid < 100) sbuf[tid] = fmaxf(part[tid] + part[tid + 100], 0.f);
    __syncthreads();
    for (int idx = tid; idx < 1600; idx += 256) {
        int o = idx / 25, v = idx % 25;
        float z = be[o];
        #pragma unroll
        for (int r = 0; r < 4; r++)
            z = fmaf(sbuf[r * 25 + v], we[o * 4 + r], z);
        d_g[n * 1600 + idx] = 1.f + 1.f / (1.f + expf(-z));
    }
}

// ------------------------------- final --------------------------------------
__global__ void final_kernel(float* __restrict__ out)
{
    unsigned i = blockIdx.x * blockDim.x + threadIdx.x;
    float4 v = reinterpret_cast<float4*>(out)[i];
    unsigned flat = i * 4u;
    unsigned q  = flat / 25u;
    unsigned v0 = flat - q * 25u;
    unsigned co = q / 256u;
    const float* gr = d_g + (size_t)co * 25u;
    unsigned v1 = v0 + 1u; if (v1 >= 25u) v1 -= 25u;
    unsigned v2 = v0 + 2u; if (v2 >= 25u) v2 -= 25u;
    unsigned v3 = v0 + 3u; if (v3 >= 25u) v3 -= 25u;
    v.x *= gr[v0]; v.y *= gr[v1]; v.z *= gr[v2]; v.w *= gr[v3];
    reinterpret_cast<float4*>(out)[i] = v;
}

// ------------------------------ launcher -------------------------------------
extern "C" void kernel_launch(void* const* d_in, const int* in_sizes, int n_in,
                              void* d_out, int out_size)
{
    const float* x     = (const float*)d_in[0];
    const float* A     = (const float*)d_in[1];
    const float* PA    = (const float*)d_in[2];
    const float* wd    = (const float*)d_in[3];
    const float* bd    = (const float*)d_in[4];
    const float* gamma = (const float*)d_in[5];
    const float* beta  = (const float*)d_in[6];
    const float* mean  = (const float*)d_in[7];
    const float* var   = (const float*)d_in[8];
    const float* sws   = (const float*)d_in[9];
    const float* sbs   = (const float*)d_in[10];
    const float* swe   = (const float*)d_in[11];
    const float* sbe   = (const float*)d_in[12];
    float* out = (float*)d_out;

    cudaFuncSetAttribute(main_kernel, cudaFuncAttributeMaxDynamicSharedMemorySize,
                         SMEM_BYTES);

    prep1_kernel<<<1, 256>>>(A, PA, bd, gamma, beta, mean, var);
    prep2_kernel<<<64, 256>>>(wd, gamma, var);
    dim3 grid(64, 128);
    main_kernel<<<grid, 256, SMEM_BYTES>>>(x, out);
    gate_kernel<<<128, 256>>>(sws, sbs, swe, sbe);
    final_kernel<<<51200, 256>>>(out);
}

// round 17
// speedup vs baseline: 1.1376x; 1.0104x over previous
#include <cuda_runtime.h>
#include <cuda_bf16.h>
#include <math.h>
#include <stdint.h>

// ---------------------------------------------------------------------------
// unit_gcn: stage-1 HMMA (mma.sync m16n8k16 bf16, 3-term split via K-concat,
// two A halves, cp.async fills, B' seg-dedup [Xhi|Xlo]), stage-2 scalar f32x2
// with t-pairing, smem-staged coalesced epilogue.  4 frames/block, 256 thr,
// 2 CTAs/SM.  R17: d_pp reduction split into bandwidth-shaped kernel.
// ---------------------------------------------------------------------------

typedef unsigned long long ull;

__device__ __forceinline__ ull pk2(float lo, float hi) {
    ull r; asm("mov.b64 %0, {%1, %2};" : "=l"(r) : "f"(lo), "f"(hi)); return r;
}
__device__ __forceinline__ void fma2(ull &d, ull a, ull b) {
    asm("fma.rn.f32x2 %0, %1, %2, %0;" : "+l"(d) : "l"(a), "l"(b));
}
__device__ __forceinline__ float2 up2(ull v) {
    float2 r; asm("mov.b64 {%0, %1}, %2;" : "=f"(r.x), "=f"(r.y) : "l"(v)); return r;
}
__device__ __forceinline__ uint32_t smem_u32(const void* p) {
    uint32_t a;
    asm("{ .reg .u64 t; cvta.to.shared.u64 t, %1; cvt.u32.u64 %0, t; }"
        : "=r"(a) : "l"(p));
    return a;
}
__device__ __forceinline__ void cp16(uint32_t dst, const void* src) {
    asm volatile("cp.async.cg.shared.global [%0], [%1], 16;"
                 :: "r"(dst), "l"(src) : "memory");
}
__device__ __forceinline__ void cp_commit_wait() {
    asm volatile("cp.async.commit_group;" ::: "memory");
    asm volatile("cp.async.wait_group 0;" ::: "memory");
}
__device__ __forceinline__ void ldsm_x4(uint32_t &r0, uint32_t &r1,
                                        uint32_t &r2, uint32_t &r3, uint32_t a) {
    asm volatile("ldmatrix.sync.aligned.m8n8.x4.shared.b16 {%0,%1,%2,%3}, [%4];"
                 : "=r"(r0), "=r"(r1), "=r"(r2), "=r"(r3) : "r"(a));
}
__device__ __forceinline__ void ldsm_x2(uint32_t &r0, uint32_t &r1, uint32_t a) {
    asm volatile("ldmatrix.sync.aligned.m8n8.x2.shared.b16 {%0,%1}, [%2];"
                 : "=r"(r0), "=r"(r1) : "r"(a));
}
__device__ __forceinline__ void mma_bf16(float* d, const uint32_t* a,
                                         uint32_t b0, uint32_t b1) {
    asm volatile(
        "mma.sync.aligned.m16n8k16.row.col.f32.bf16.bf16.f32 "
        "{%0,%1,%2,%3}, {%4,%5,%6,%7}, {%8,%9}, {%0,%1,%2,%3};"
        : "+f"(d[0]), "+f"(d[1]), "+f"(d[2]), "+f"(d[3])
        : "r"(a[0]), "r"(a[1]), "r"(a[2]), "r"(a[3]), "r"(b0), "r"(b1));
}

// ------------------------- smem layout (bytes) ------------------------------
#define AH_OFF     0
#define AH_BYTES   39936
#define B_OFF      39936
#define B_PITCH    272
#define AFS_OFF    89088
#define KC_OFF     97488
#define SMEM_BYTES 97792
#define P_OFF      0
#define P_STRIDE   116
#define YS_OFF     0               /* ys[64][100] f32, overlays P after stage2 */

// ------------------------- device scratch (no allocs) ----------------------
__device__ __nv_bfloat16 d_Aimg2[2 * 192 * 104]; // A' per k-half, row pitch 104
__device__ float d_Afp[75 * 28];                 // Af padded stride 28
__device__ float d_Kc[64];
__device__ float d_pp[64 * 128 * 1600];          // per-(ttile,n) partial sums
__device__ float d_pm[128 * 1600];               // reduced T-means
__device__ float d_g[128 * 64 * 25];

// ------------------------------- prep1 (serial small parts) ----------------
__global__ void prep1_kernel(const float* __restrict__ A, const float* __restrict__ PA,
                             const float* __restrict__ bd,
                             const float* __restrict__ gamma, const float* __restrict__ beta,
                             const float* __restrict__ mean, const float* __restrict__ var)
{
    int tid = threadIdx.x;
    if (tid < 64) {
        float sc = gamma[tid] * rsqrtf(var[tid] + 1e-5f);
        d_Kc[tid] = (bd[tid] + bd[64 + tid] + bd[128 + tid]) * sc
                    + beta[tid] - mean[tid] * sc;
    }
    for (int idx = tid; idx < 75; idx += blockDim.x) {
        int s = idx / 25, w = idx % 25;
        float nrm = 0.f;
        for (int v = 0; v < 25; v++) {
            float pv = PA[(s * 25 + v) * 25 + w];
            nrm += pv * pv;
        }
        nrm = sqrtf(nrm) + 1e-4f;
        for (int v = 0; v < 25; v++)
            d_Afp[(s * 25 + v) * 28 + w] =
                A[(s * 25 + v) * 25 + w] + PA[(s * 25 + v) * 25 + w] / nrm;
        d_Afp[idx * 28 + 25] = 0.f;
        d_Afp[idx * 28 + 26] = 0.f;
        d_Afp[idx * 28 + 27] = 0.f;
    }
}

// ------------------------------- prep2 (parallel A' image) -----------------
__global__ void prep2_kernel(const float* __restrict__ wd,
                             const float* __restrict__ gamma,
                             const float* __restrict__ var)
{
    const int stride = gridDim.x * blockDim.x;
    for (int e = blockIdx.x * blockDim.x + threadIdx.x; e < 2 * 192 * 104;
         e += stride) {
        int h   = e / (192 * 104);
        int rem = e - h * 192 * 104;
        int row = rem / 104, kc = rem - row * 104;
        float val = 0.f;
        if (kc < 96) {
            int k = h * 96 + kc;
            int s = row >> 6, o = row & 63;
            int seg = k >> 6, c = k & 63;
            float sc = gamma[o] * rsqrtf(var[o] + 1e-5f);
            float w = wd[(s * 64 + o) * 64 + c] * sc;
            float hi = __bfloat162float(__float2bfloat16(w));
            val = (seg < 2) ? hi : (w - hi);
        }
        d_Aimg2[e] = __float2bfloat16(val);
    }
}

// ------------------------------- main ---------------------------------------
__global__ void __launch_bounds__(256, 2)
main_kernel(const float* __restrict__ x, float* __restrict__ out)
{
    extern __shared__ char smc[];
    const uint32_t smb = smem_u32(smc);
    const int tid  = threadIdx.x;
    const int wrp  = tid >> 5;
    const int lane = tid & 31;
    const int n    = blockIdx.y;
    const int t0   = blockIdx.x * 4;

    // ---- fill: A half0 via cp.async (overlaps B' conversion), B', Af, Kc ----
    {
        const char* srcA = (const char*)d_Aimg2;
        #pragma unroll
        for (int i = 0; i < 10; i++) {
            int e = (tid + i * 256) * 16;
            if (e < AH_BYTES) cp16(smb + AH_OFF + e, srcA + e);
        }
        asm volatile("cp.async.commit_group;" ::: "memory");

        const float* xb = x + (size_t)n * 409600 + t0 * 25;
        __nv_bfloat16* smB = (__nv_bfloat16*)(smc + B_OFF);
        for (int e = tid; e < 6400; e += 256) {
            int c = e / 100, r = e - c * 100;
            float xv = xb[c * 6400 + r];
            __nv_bfloat16 h = __float2bfloat16(xv);
            __nv_bfloat16 l = __float2bfloat16(xv - __bfloat162float(h));
            __nv_bfloat16* br = smB + r * 136;   // 272B pitch
            br[c]      = h;
            br[64 + c] = l;
        }
        float* Afs = (float*)(smc + AFS_OFF);
        for (int i = tid; i < 75 * 28; i += 256) Afs[i] = d_Afp[i];
        float* Kcs = (float*)(smc + KC_OFF);
        if (tid < 64) Kcs[tid] = d_Kc[tid];
        asm volatile("cp.async.wait_group 0;" ::: "memory");
    }
    __syncthreads();

    // ---- stage 1: HMMA, warp (mw,nw) owns 48 x 56 of P[192][112] ----
    const int mw = wrp >> 1;
    const int nw = wrp & 1;

    float acc[3][7][4];
    #pragma unroll
    for (int i = 0; i < 3; i++)
        #pragma unroll
        for (int j = 0; j < 7; j++)
            #pragma unroll
            for (int q = 0; q < 4; q++) acc[i][j][q] = 0.f;

    const uint32_t aLane = (((lane & 7) + ((lane >> 3) & 1) * 8) * 208
                            + ((lane >> 4) & 1) * 16);
    const uint32_t aBase = smb + AH_OFF + (uint32_t)(mw * 48) * 208u + aLane;
    const uint32_t bLane4 = ((lane & 7) * B_PITCH + ((lane >> 3) & 1) * 16
                             + ((lane >> 4) & 1) * (8 * B_PITCH));
    const uint32_t bBase4 = smb + B_OFF + (uint32_t)(nw * 56) * B_PITCH + bLane4;
    const uint32_t bBase2 = smb + B_OFF + (uint32_t)(nw * 56 + 48) * B_PITCH
                            + (lane & 7) * B_PITCH + ((lane >> 3) & 1) * 16;

    #pragma unroll
    for (int h = 0; h < 2; h++) {
        if (h == 1) {
            __syncthreads();       // half-0 ldsm reads done
            const char* srcA = (const char*)d_Aimg2 + AH_BYTES;
            #pragma unroll
            for (int i = 0; i < 10; i++) {
                int e = (tid + i * 256) * 16;
                if (e < AH_BYTES) cp16(smb + AH_OFF + e, srcA + e);
            }
            cp_commit_wait();
            __syncthreads();
        }
        #pragma unroll 2
        for (int ksl = 0; ksl < 6; ksl++) {
            const int step = h * 6 + ksl;
            const uint32_t ko = (uint32_t)ksl * 32u;
            const uint32_t kb = (uint32_t)((step < 8 ? step : step - 8) * 32);
            uint32_t af[3][4];
            #pragma unroll
            for (int i = 0; i < 3; i++)
                ldsm_x4(af[i][0], af[i][1], af[i][2], af[i][3],
                        aBase + (uint32_t)i * 3328u + ko);
            #pragma unroll
            for (int jj = 0; jj < 3; jj++) {
                uint32_t q0, q1, q2, q3;
                ldsm_x4(q0, q1, q2, q3,
                        bBase4 + (uint32_t)jj * (16 * B_PITCH) + kb);
                #pragma unroll
                for (int i = 0; i < 3; i++) {
                    mma_bf16(acc[i][2 * jj],     af[i], q0, q1);
                    mma_bf16(acc[i][2 * jj + 1], af[i], q2, q3);
                }
            }
            {
                uint32_t b0, b1;
                ldsm_x2(b0, b1, bBase2 + kb);
                #pragma unroll
                for (int i = 0; i < 3; i++)
                    mma_bf16(acc[i][6], af[i], b0, b1);
            }
        }
    }
    __syncthreads();   // all ldsm reads done; A/B region dead

    // ---- write P[192][116] f32 ----
    float* Psf = (float*)(smc + P_OFF);
    {
        const int rl = lane >> 2;
        const int cl = (lane & 3) * 2;
        #pragma unroll
        for (int i = 0; i < 3; i++) {
            int r0 = mw * 48 + i * 16 + rl;
            #pragma unroll
            for (int j = 0; j < 7; j++) {
                int c = nw * 56 + j * 8 + cl;
                *(float2*)&Psf[r0 * P_STRIDE + c] =
                    make_float2(acc[i][j][0], acc[i][j][1]);
                *(float2*)&Psf[(r0 + 8) * P_STRIDE + c] =
                    make_float2(acc[i][j][2], acc[i][j][3]);
            }
        }
    }
    __syncthreads();

    // ---- stage 2 (t-paired): thread = (o, t-half); 128 active threads ----
    const int o  = (tid >> 1) & 63;
    const int th = tid & 1;              // frames 2*th, 2*th+1

    ull yacc[2][13];
    if (tid < 128) {
        #pragma unroll
        for (int u = 0; u < 2; u++)
            #pragma unroll
            for (int wp = 0; wp < 13; wp++) yacc[u][wp] = 0ull;

        const float* Afs = (const float*)(smc + AFS_OFF);
        #pragma unroll
        for (int s = 0; s < 3; s++) {
            const float* pb = Psf + (s * 64 + o) * P_STRIDE + (2 * th) * 25;
            const char* afb = (const char*)(Afs + s * 25 * 28);
            #pragma unroll 5
            for (int v = 0; v < 25; v++) {
                const char* ar = afb + v * 112;
                ulonglong2 q0 = *(const ulonglong2*)(ar);
                ulonglong2 q1 = *(const ulonglong2*)(ar + 16);
                ulonglong2 q2 = *(const ulonglong2*)(ar + 32);
                ulonglong2 q3 = *(const ulonglong2*)(ar + 48);
                ulonglong2 q4 = *(const ulonglong2*)(ar + 64);
                ulonglong2 q5 = *(const ulonglong2*)(ar + 80);
                ull q6 = *(const ull*)(ar + 96);
                float pf0 = pb[v];
                float pf1 = pb[25 + v];
                ull pv0 = pk2(pf0, pf0);
                ull pv1 = pk2(pf1, pf1);
                fma2(yacc[0][0],  pv0, q0.x);  fma2(yacc[0][1],  pv0, q0.y);
                fma2(yacc[0][2],  pv0, q1.x);  fma2(yacc[0][3],  pv0, q1.y);
                fma2(yacc[0][4],  pv0, q2.x);  fma2(yacc[0][5],  pv0, q2.y);
                fma2(yacc[0][6],  pv0, q3.x);  fma2(yacc[0][7],  pv0, q3.y);
                fma2(yacc[0][8],  pv0, q4.x);  fma2(yacc[0][9],  pv0, q4.y);
                fma2(yacc[0][10], pv0, q5.x);  fma2(yacc[0][11], pv0, q5.y);
                fma2(yacc[0][12], pv0, q6);
                fma2(yacc[1][0],  pv1, q0.x);  fma2(yacc[1][1],  pv1, q0.y);
                fma2(yacc[1][2],  pv1, q1.x);  fma2(yacc[1][3],  pv1, q1.y);
                fma2(yacc[1][4],  pv1, q2.x);  fma2(yacc[1][5],  pv1, q2.y);
                fma2(yacc[1][6],  pv1, q3.x);  fma2(yacc[1][7],  pv1, q3.y);
                fma2(yacc[1][8],  pv1, q4.x);  fma2(yacc[1][9],  pv1, q4.y);
                fma2(yacc[1][10], pv1, q5.x);  fma2(yacc[1][11], pv1, q5.y);
                fma2(yacc[1][12], pv1, q6);
            }
        }
    }
    __syncthreads();          // all P reads done; overlay ys on P region

    // ---- stage 2b: dump raw y to ys[64][100] ----
    float* ys = (float*)(smc + YS_OFF);
    if (tid < 128) {
        #pragma unroll
        for (int u = 0; u < 2; u++) {
            float* yr = ys + o * 100 + (2 * th + u) * 25;
            #pragma unroll
            for (int wp = 0; wp < 12; wp++) {
                float2 t2 = up2(yacc[u][wp]);
                yr[2 * wp]     = t2.x;
                yr[2 * wp + 1] = t2.y;
            }
            yr[24] = up2(yacc[u][12]).x;
        }
    }
    __syncthreads();

    // ---- epilogue pass (coalesced): yfinal = relu(y + kc + x); store out ----
    {
        const float* Kcs = (const float*)(smc + KC_OFF);
        const float* xb = x + (size_t)n * 409600 + t0 * 25;
        float* ob = out + (size_t)n * 409600 + t0 * 25;
        #pragma unroll
        for (int e = tid; e < 6400; e += 256) {
            int oo = e / 100, r = e - oo * 100;
            float yf = fmaxf(ys[e] + Kcs[oo] + xb[oo * 6400 + r], 0.f);
            ob[oo * 6400 + r] = yf;
            ys[e] = yf;
        }
    }
    __syncthreads();

    // ---- T-sum pass: d_pp[(blk,n)][o*25+w] = sum_t ys[o][t*25+w] ----
    {
        float* pout = d_pp + ((size_t)blockIdx.x * 128 + n) * 1600;
        for (int idx = tid; idx < 1600; idx += 256) {
            int oo = idx / 25, w = idx - oo * 25;
            const float* yr = ys + oo * 100 + w;
            pout[idx] = (yr[0] + yr[25]) + (yr[50] + yr[75]);
        }
    }
}

// -------------------- reduce d_pp -> d_pm (bandwidth-shaped) -----------------
// 800 blocks x 256 threads: one thread per (n, idx) element.
__global__ void reduce_pp_kernel()
{
    int e = blockIdx.x * blockDim.x + threadIdx.x;   // 0 .. 204799
    int n = e / 1600, idx = e - n * 1600;
    float a0 = 0.f, a1 = 0.f, a2 = 0.f, a3 = 0.f;
    for (int tile = 0; tile < 64; tile += 4) {
        a0 += d_pp[((size_t)(tile + 0) * 128 + n) * 1600 + idx];
        a1 += d_pp[((size_t)(tile + 1) * 128 + n) * 1600 + idx];
        a2 += d_pp[((size_t)(tile + 2) * 128 + n) * 1600 + idx];
        a3 += d_pp[((size_t)(tile + 3) * 128 + n) * 1600 + idx];
    }
    d_pm[e] = ((a0 + a1) + (a2 + a3)) * (1.0f / 256.0f);
}

// ------------------------------- gate ---------------------------------------
__global__ void gate_kernel(const float* __restrict__ ws, const float* __restrict__ bs,
                            const float* __restrict__ we, const float* __restrict__ be)
{
    __shared__ float p[1600];
    __shared__ float part[200];
    __shared__ float sbuf[100];
    const int n = blockIdx.x, tid = threadIdx.x;   // 256 threads
    for (int idx = tid; idx < 1600; idx += 256)
        p[idx] = d_pm[n * 1600 + idx];
    __syncthreads();
    // conv spread over 200 threads: worker = (rv, c-half of 32)
    if (tid < 200) {
        int half = tid / 100;
        int rv = tid - half * 100;
        int r = rv / 25, v = rv % 25;
        float acc = (half == 0) ? bs[r] : 0.f;
        int k0 = 12 - v; if (k0 < 0) k0 = 0;
        int k1 = 36 - v; if (k1 > 24) k1 = 24;
        int c0 = half * 32;
        for (int c = c0; c < c0 + 32; c++) {
            const float* wr = &ws[(r * 64 + c) * 25];
            const float* pc = &p[c * 25 + v - 12];
            for (int k = k0; k <= k1; k++)
                acc = fmaf(pc[k], wr[k], acc);
        }
        part[tid] = acc;
    }
    __syncthreads();
    if (tid < 100) sbuf[tid] = fmaxf(part[tid] + part[tid + 100], 0.f);
    __syncthreads();
    for (int idx = tid; idx < 1600; idx += 256) {
        int o = idx / 25, v = idx % 25;
        float z = be[o];
        #pragma unroll
        for (int r = 0; r < 4; r++)
            z = fmaf(sbuf[r * 25 + v], we[o * 4 + r], z);
        d_g[n * 1600 + idx] = 1.f + 1.f / (1.f + expf(-z));
    }
}

// ------------------------------- final --------------------------------------
__global__ void final_kernel(float* __restrict__ out)
{
    unsigned i = blockIdx.x * blockDim.x + threadIdx.x;
    float4 v = reinterpret_cast<float4*>(out)[i];
    unsigned flat = i * 4u;
    unsigned q  = flat / 25u;
    unsigned v0 = flat - q * 25u;
    unsigned co = q / 256u;
    const float* gr = d_g + (size_t)co * 25u;
    unsigned v1 = v0 + 1u; if (v1 >= 25u) v1 -= 25u;
    unsigned v2 = v0 + 2u; if (v2 >= 25u) v2 -= 25u;
    unsigned v3 = v0 + 3u; if (v3 >= 25u) v3 -= 25u;
    v.x *= gr[v0]; v.y *= gr[v1]; v.z *= gr[v2]; v.w *= gr[v3];
    reinterpret_cast<float4*>(out)[i] = v;
}

// ------------------------------ launcher -------------------------------------
extern "C" void kernel_launch(void* const* d_in, const int* in_sizes, int n_in,
                              void* d_out, int out_size)
{
    const float* x     = (const float*)d_in[0];
    const float* A     = (const float*)d_in[1];
    const float* PA    = (const float*)d_in[2];
    const float* wd    = (const float*)d_in[3];
    const float* bd    = (const float*)d_in[4];
    const float* gamma = (const float*)d_in[5];
    const float* beta  = (const float*)d_in[6];
    const float* mean  = (const float*)d_in[7];
    const float* var   = (const float*)d_in[8];
    const float* sws   = (const float*)d_in[9];
    const float* sbs   = (const float*)d_in[10];
    const float* swe   = (const float*)d_in[11];
    const float* sbe   = (const float*)d_in[12];
    float* out = (float*)d_out;

    cudaFuncSetAttribute(main_kernel, cudaFuncAttributeMaxDynamicSharedMemorySize,
                         SMEM_BYTES);

    prep1_kernel<<<1, 256>>>(A, PA, bd, gamma, beta, mean, var);
    prep2_kernel<<<64, 256>>>(wd, gamma, var);
    dim3 grid(64, 128);
    main_kernel<<<grid, 256, SMEM_BYTES>>>(x, out);
    reduce_pp_kernel<<<800, 256>>>();
    gate_kernel<<<128, 256>>>(sws, sbs, swe, sbe);
    final_kernel<<<51200, 256>>>(out);
}